// round 1
// baseline (speedup 1.0000x reference)
#include <cuda_runtime.h>
#include <math.h>

#define N_NODES 50000
#define N_EDGES 800000
#define HH 256          // HEADS*HIDDEN = heads*hidden flattened feature dim
#define NHEADS 4

// ---------------- scratch (no allocations allowed) ----------------
__device__ float g_h  [(size_t)N_NODES * HH];   // GEMM output (pre-attention features)
__device__ float g_h2 [(size_t)N_NODES * HH];   // layer output (post-ELU) / next input
__device__ float g_el [N_NODES * NHEADS];
__device__ float g_er [N_NODES * NHEADS];
__device__ int   g_rowptr[N_NODES + 1];
__device__ int   g_counts[N_NODES];
__device__ int   g_csr_src[N_EDGES];

// ---------------- CSR build ----------------
__global__ void zero_counts_k() {
    int i = blockIdx.x * blockDim.x + threadIdx.x;
    if (i < N_NODES) g_counts[i] = 0;
}

__global__ void hist_k(const int* __restrict__ dst, int E) {
    int i = blockIdx.x * blockDim.x + threadIdx.x;
    if (i < E) atomicAdd(&g_counts[dst[i]], 1);
}

// single-block scan over 50000 counts -> rowptr
__global__ void scan_k() {
    __shared__ int part[1024];
    const int C = (N_NODES + 1023) / 1024;  // 49
    int t = threadIdx.x;
    int base = t * C;
    int s = 0;
    for (int i = 0; i < C; i++) {
        int id = base + i;
        if (id < N_NODES) s += g_counts[id];
    }
    part[t] = s;
    __syncthreads();
    for (int off = 1; off < 1024; off <<= 1) {
        int v = (t >= off) ? part[t - off] : 0;
        __syncthreads();
        part[t] += v;
        __syncthreads();
    }
    int run = (t == 0) ? 0 : part[t - 1];
    for (int i = 0; i < C; i++) {
        int id = base + i;
        if (id < N_NODES) {
            g_rowptr[id] = run;
            run += g_counts[id];
        }
    }
    if (t == 1023) g_rowptr[N_NODES] = part[1023];
}

__global__ void scatter_k(const int* __restrict__ src, const int* __restrict__ dst, int E) {
    int i = blockIdx.x * blockDim.x + threadIdx.x;
    if (i < E) {
        int d = dst[i];
        int pos = g_rowptr[d] + atomicAdd(&g_counts[d], 1);
        g_csr_src[pos] = src[i];
    }
}

// ---------------- GEMM: C[N,256] = A[N,K] @ B[K,256], fp32 ----------------
#define BM 64
#define BN 64
#define BK 32

__global__ void __launch_bounds__(256) gemm_k(const float* __restrict__ A,
                                              const float* __restrict__ B,
                                              float* __restrict__ C,
                                              int N, int K) {
    __shared__ float As[BM][BK + 1];
    __shared__ float Bs[BK][BN];
    int row0 = blockIdx.y * BM;
    int col0 = blockIdx.x * BN;
    int tid = threadIdx.x;
    int tx = tid & 15;
    int ty = tid >> 4;
    float acc[4][4];
#pragma unroll
    for (int i = 0; i < 4; i++)
#pragma unroll
        for (int j = 0; j < 4; j++) acc[i][j] = 0.f;

    for (int k0 = 0; k0 < K; k0 += BK) {
        // load A tile: 64x32, 256 threads x 2 float4
        {
            int r = tid >> 3;           // 0..31
            int kq = (tid & 7) * 4;     // 0..28
#pragma unroll
            for (int p = 0; p < 2; p++) {
                int rr = r + p * 32;
                int grow = row0 + rr;
                float4 v = make_float4(0.f, 0.f, 0.f, 0.f);
                if (grow < N) v = *(const float4*)(A + (size_t)grow * K + k0 + kq);
                As[rr][kq + 0] = v.x;
                As[rr][kq + 1] = v.y;
                As[rr][kq + 2] = v.z;
                As[rr][kq + 3] = v.w;
            }
        }
        // load B tile: 32x64
        {
            int r = tid >> 4;           // 0..15
            int cq = (tid & 15) * 4;    // 0..60
#pragma unroll
            for (int p = 0; p < 2; p++) {
                int rr = r + p * 16;
                float4 v = *(const float4*)(B + (size_t)(k0 + rr) * 256 + col0 + cq);
                *(float4*)&Bs[rr][cq] = v;
            }
        }
        __syncthreads();
#pragma unroll
        for (int kk = 0; kk < BK; kk++) {
            float a[4];
#pragma unroll
            for (int i = 0; i < 4; i++) a[i] = As[ty * 4 + i][kk];
            float4 bv = *(float4*)&Bs[kk][tx * 4];
            float b[4] = {bv.x, bv.y, bv.z, bv.w};
#pragma unroll
            for (int i = 0; i < 4; i++)
#pragma unroll
                for (int j = 0; j < 4; j++) acc[i][j] += a[i] * b[j];
        }
        __syncthreads();
    }
#pragma unroll
    for (int i = 0; i < 4; i++) {
        int grow = row0 + ty * 4 + i;
        if (grow < N) {
            float4 v = make_float4(acc[i][0], acc[i][1], acc[i][2], acc[i][3]);
            *(float4*)(C + (size_t)grow * 256 + col0 + tx * 4) = v;
        }
    }
}

// ---------------- attention scores: el[n,h]=<h[n,h,:],al[h,:]>, er likewise ----------------
__global__ void __launch_bounds__(128) attn_scores_k(const float* __restrict__ h,
                                                     const float* __restrict__ al,
                                                     const float* __restrict__ ar,
                                                     int N) {
    int w = (blockIdx.x * 128 + threadIdx.x) >> 5;
    int lane = threadIdx.x & 31;
    if (w >= N) return;
    int idx = lane * 8;  // feature index base; head = lane>>3
    const float4* hp = (const float4*)(h + (size_t)w * HH + idx);
    float4 ha = hp[0], hb = hp[1];
    const float4* alp = (const float4*)(al + idx);
    float4 aa = alp[0], ab = alp[1];
    const float4* arp = (const float4*)(ar + idx);
    float4 ra = arp[0], rb = arp[1];
    float sl = ha.x * aa.x + ha.y * aa.y + ha.z * aa.z + ha.w * aa.w +
               hb.x * ab.x + hb.y * ab.y + hb.z * ab.z + hb.w * ab.w;
    float sr = ha.x * ra.x + ha.y * ra.y + ha.z * ra.z + ha.w * ra.w +
               hb.x * rb.x + hb.y * rb.y + hb.z * rb.z + hb.w * rb.w;
#pragma unroll
    for (int off = 4; off >= 1; off >>= 1) {
        sl += __shfl_down_sync(0xffffffffu, sl, off);
        sr += __shfl_down_sync(0xffffffffu, sr, off);
    }
    if ((lane & 7) == 0) {
        int hd = lane >> 3;
        g_el[w * NHEADS + hd] = sl;
        g_er[w * NHEADS + hd] = sr;
    }
}

// ---------------- fused edge softmax + aggregate + ELU, one warp per dst node ----------------
__global__ void __launch_bounds__(128) aggregate_k(const float* __restrict__ h,
                                                   float* __restrict__ out,
                                                   int N) {
    int v = (blockIdx.x * 128 + threadIdx.x) >> 5;
    int lane = threadIdx.x & 31;
    if (v >= N) return;
    int hd = lane >> 3;  // head owned by this lane

    float4 er4 = ((const float4*)g_er)[v];
    float erv = (hd == 0) ? er4.x : (hd == 1) ? er4.y : (hd == 2) ? er4.z : er4.w;

    int r0 = g_rowptr[v];
    int r1 = g_rowptr[v + 1];

    // pass 1: max
    float m = -INFINITY;
    for (int j = r0; j < r1; j++) {
        int s = g_csr_src[j];
        float4 el4 = ((const float4*)g_el)[s];
        float elv = (hd == 0) ? el4.x : (hd == 1) ? el4.y : (hd == 2) ? el4.z : el4.w;
        float e = elv + erv;
        e = (e > 0.f) ? e : 0.2f * e;
        m = fmaxf(m, e);
    }

    // pass 2: weighted accumulate + denominator
    float ssum = 0.f;
    float4 acca = make_float4(0.f, 0.f, 0.f, 0.f);
    float4 accb = make_float4(0.f, 0.f, 0.f, 0.f);
    for (int j = r0; j < r1; j++) {
        int s = g_csr_src[j];
        float4 el4 = ((const float4*)g_el)[s];
        float elv = (hd == 0) ? el4.x : (hd == 1) ? el4.y : (hd == 2) ? el4.z : el4.w;
        float e = elv + erv;
        e = (e > 0.f) ? e : 0.2f * e;
        float wgt = __expf(e - m);
        ssum += wgt;
        const float4* hp = (const float4*)(h + (size_t)s * HH + lane * 8);
        float4 ha = hp[0], hb = hp[1];
        acca.x += wgt * ha.x; acca.y += wgt * ha.y;
        acca.z += wgt * ha.z; acca.w += wgt * ha.w;
        accb.x += wgt * hb.x; accb.y += wgt * hb.y;
        accb.z += wgt * hb.z; accb.w += wgt * hb.w;
    }

    float inv = 1.f / (ssum + 1e-9f);
    float o[8] = {acca.x * inv, acca.y * inv, acca.z * inv, acca.w * inv,
                  accb.x * inv, accb.y * inv, accb.z * inv, accb.w * inv};
#pragma unroll
    for (int i = 0; i < 8; i++) o[i] = (o[i] > 0.f) ? o[i] : expm1f(o[i]);

    float* op = out + (size_t)v * HH + lane * 8;
    *(float4*)(op + 0) = make_float4(o[0], o[1], o[2], o[3]);
    *(float4*)(op + 4) = make_float4(o[4], o[5], o[6], o[7]);
}

// ---------------- final head: relu(mean_h(feats) @ Wout + bout) ----------------
__global__ void __launch_bounds__(128) final_k(const float* __restrict__ feats,
                                               const float* __restrict__ Wout,
                                               const float* __restrict__ bout,
                                               float* __restrict__ out,
                                               int N) {
    int v = (blockIdx.x * 128 + threadIdx.x) >> 5;
    int lane = threadIdx.x & 31;
    if (v >= N) return;
    int idx = lane * 8;
    const float4* fp = (const float4*)(feats + (size_t)v * HH + idx);
    float4 fa = fp[0], fb = fp[1];
    const float4* wp = (const float4*)(Wout + (idx & 63));
    float4 wa = wp[0], wb = wp[1];
    float s = fa.x * wa.x + fa.y * wa.y + fa.z * wa.z + fa.w * wa.w +
              fb.x * wb.x + fb.y * wb.y + fb.z * wb.z + fb.w * wb.w;
#pragma unroll
    for (int off = 16; off >= 1; off >>= 1) s += __shfl_down_sync(0xffffffffu, s, off);
    if (lane == 0) {
        float r = 0.25f * s + bout[0];
        out[v] = (r > 0.f) ? r : 0.f;
    }
}

// ---------------- launch ----------------
extern "C" void kernel_launch(void* const* d_in, const int* in_sizes, int n_in,
                              void* d_out, int out_size) {
    const float* x    = (const float*)d_in[0];
    const int*   src  = (const int*)d_in[1];
    const int*   dst  = (const int*)d_in[2];
    const float* W0   = (const float*)d_in[3];
    const float* al0  = (const float*)d_in[4];
    const float* ar0  = (const float*)d_in[5];
    const float* W1   = (const float*)d_in[6];
    const float* al1  = (const float*)d_in[7];
    const float* ar1  = (const float*)d_in[8];
    const float* W2   = (const float*)d_in[9];
    const float* al2  = (const float*)d_in[10];
    const float* ar2  = (const float*)d_in[11];
    const float* Wout = (const float*)d_in[12];
    const float* bout = (const float*)d_in[13];

    const int N = N_NODES;
    const int E = N_EDGES;

    float *h, *h2;
    cudaGetSymbolAddress((void**)&h, g_h);
    cudaGetSymbolAddress((void**)&h2, g_h2);

    // build CSR (dst-sorted)
    zero_counts_k<<<(N + 255) / 256, 256>>>();
    hist_k<<<(E + 255) / 256, 256>>>(dst, E);
    scan_k<<<1, 1024>>>();
    zero_counts_k<<<(N + 255) / 256, 256>>>();  // reset cursors
    scatter_k<<<(E + 255) / 256, 256>>>(src, dst, E);

    dim3 ggrid(256 / BN, (N + BM - 1) / BM);
    int warpGrid = (N + 3) / 4;

    // layer 0
    gemm_k<<<ggrid, 256>>>(x, W0, h, N, 128);
    attn_scores_k<<<warpGrid, 128>>>(h, al0, ar0, N);
    aggregate_k<<<warpGrid, 128>>>(h, h2, N);
    // layer 1
    gemm_k<<<ggrid, 256>>>(h2, W1, h, N, 256);
    attn_scores_k<<<warpGrid, 128>>>(h, al1, ar1, N);
    aggregate_k<<<warpGrid, 128>>>(h, h2, N);
    // layer 2
    gemm_k<<<ggrid, 256>>>(h2, W2, h, N, 256);
    attn_scores_k<<<warpGrid, 128>>>(h, al2, ar2, N);
    aggregate_k<<<warpGrid, 128>>>(h, h2, N);
    // output head
    final_k<<<warpGrid, 128>>>(h2, Wout, bout, (float*)d_out, N);
}

// round 3
// speedup vs baseline: 1.2803x; 1.2803x over previous
#include <cuda_runtime.h>
#include <cuda_bf16.h>
#include <math.h>
#include <stdint.h>

#define N_NODES 50000
#define N_EDGES 800000
#define HH 256
#define NHEADS 4
#define MPAD 50048

// ---------------- scratch ----------------
__device__ float g_h  [(size_t)N_NODES * HH];
__device__ float g_h2 [(size_t)N_NODES * HH];
__device__ float g_el [N_NODES * NHEADS];
__device__ float g_er [N_NODES * NHEADS];
__device__ int   g_rowptr[N_NODES + 1];
__device__ int   g_counts[N_NODES];
__device__ int   g_csr_src[N_EDGES];
__device__ __nv_bfloat16 g_a_hi[(size_t)MPAD * 256];
__device__ __nv_bfloat16 g_a_lo[(size_t)MPAD * 256];
__device__ __nv_bfloat16 g_w_hi[3 * 256 * 256];   // W^T per layer, [n][k]
__device__ __nv_bfloat16 g_w_lo[3 * 256 * 256];

// ---------------- CSR build ----------------
__global__ void zero_counts_k() {
    int i = blockIdx.x * blockDim.x + threadIdx.x;
    if (i < N_NODES) g_counts[i] = 0;
}
__global__ void hist_k(const int* __restrict__ dst, int E) {
    int i = blockIdx.x * blockDim.x + threadIdx.x;
    if (i < E) atomicAdd(&g_counts[dst[i]], 1);
}
__global__ void scan_k() {
    __shared__ int part[1024];
    const int C = (N_NODES + 1023) / 1024;
    int t = threadIdx.x;
    int base = t * C;
    int s = 0;
    for (int i = 0; i < C; i++) { int id = base + i; if (id < N_NODES) s += g_counts[id]; }
    part[t] = s;
    __syncthreads();
    for (int off = 1; off < 1024; off <<= 1) {
        int v = (t >= off) ? part[t - off] : 0;
        __syncthreads();
        part[t] += v;
        __syncthreads();
    }
    int run = (t == 0) ? 0 : part[t - 1];
    for (int i = 0; i < C; i++) {
        int id = base + i;
        if (id < N_NODES) { g_rowptr[id] = run; run += g_counts[id]; }
    }
    if (t == 1023) g_rowptr[N_NODES] = part[1023];
}
__global__ void scatter_k(const int* __restrict__ src, const int* __restrict__ dst, int E) {
    int i = blockIdx.x * blockDim.x + threadIdx.x;
    if (i < E) {
        int d = dst[i];
        int pos = g_rowptr[d] + atomicAdd(&g_counts[d], 1);
        g_csr_src[pos] = src[i];
    }
}

// ---------------- conversions ----------------
__global__ void convert_x_k(const float* __restrict__ x, int total) {
    int i = blockIdx.x * blockDim.x + threadIdx.x;
    if (i >= total) return;
    float a = x[i];
    __nv_bfloat16 hi = __float2bfloat16(a);
    __nv_bfloat16 lo = __float2bfloat16(a - __bfloat162float(hi));
    g_a_hi[i] = hi;
    g_a_lo[i] = lo;
}
__global__ void convert_w_k(const float* __restrict__ W, int K,
                            __nv_bfloat16* __restrict__ oh, __nv_bfloat16* __restrict__ ol) {
    int i = blockIdx.x * blockDim.x + threadIdx.x;
    if (i >= K * 256) return;
    int k = i / 256, n = i % 256;
    float a = W[i];
    __nv_bfloat16 hi = __float2bfloat16(a);
    __nv_bfloat16 lo = __float2bfloat16(a - __bfloat162float(hi));
    oh[(size_t)n * K + k] = hi;
    ol[(size_t)n * K + k] = lo;
}
__global__ void zero_scores_k() {
    int i = blockIdx.x * blockDim.x + threadIdx.x;
    if (i < N_NODES * NHEADS) { g_el[i] = 0.f; g_er[i] = 0.f; }
}

// ---------------- warp-MMA helpers ----------------
__device__ __forceinline__ void ldsm4(uint32_t (&r)[4], uint32_t addr) {
    asm volatile("ldmatrix.sync.aligned.m8n8.x4.shared.b16 {%0,%1,%2,%3}, [%4];"
                 : "=r"(r[0]), "=r"(r[1]), "=r"(r[2]), "=r"(r[3]) : "r"(addr));
}
__device__ __forceinline__ void mma16816(float (&d)[4], const uint32_t (&a)[4],
                                         uint32_t b0, uint32_t b1) {
    asm volatile(
        "mma.sync.aligned.m16n8k16.row.col.f32.bf16.bf16.f32 "
        "{%0,%1,%2,%3}, {%4,%5,%6,%7}, {%8,%9}, {%0,%1,%2,%3};"
        : "+f"(d[0]), "+f"(d[1]), "+f"(d[2]), "+f"(d[3])
        : "r"(a[0]), "r"(a[1]), "r"(a[2]), "r"(a[3]), "r"(b0), "r"(b1));
}

// ---------------- tensor-core GEMM: C[M,256] = A[M,K] @ W^T[256,K]^T + fused el/er ----------------
// block tile: 128 (M) x 128 (N); 8 warps: warp_m = wid&3 (32 rows), warp_n = wid>>2 (64 cols)
// smem rows padded to 80B (start-bank rotation => conflict-free ldmatrix)
#define LDA 80

template <int K>
__global__ void __launch_bounds__(256) gemm_mma_k(
    const __nv_bfloat16* __restrict__ Ah, const __nv_bfloat16* __restrict__ Al,
    const __nv_bfloat16* __restrict__ Bh, const __nv_bfloat16* __restrict__ Bl,
    float* __restrict__ C, const float* __restrict__ alw, const float* __restrict__ arw)
{
    __shared__ __align__(16) uint8_t sAh[128 * LDA];
    __shared__ __align__(16) uint8_t sAl[128 * LDA];
    __shared__ __align__(16) uint8_t sBh[128 * LDA];
    __shared__ __align__(16) uint8_t sBl[128 * LDA];

    const int t = threadIdx.x;
    const int wid = t >> 5, lane = t & 31;
    const int warp_m = wid & 3, warp_n = wid >> 2;
    const int row0 = blockIdx.y * 128;
    const int nbase = blockIdx.x * 128;

    float acc[2][8][4];
#pragma unroll
    for (int i = 0; i < 2; i++)
#pragma unroll
        for (int j = 0; j < 8; j++)
#pragma unroll
            for (int q = 0; q < 4; q++) acc[i][j][q] = 0.f;

    // smem u32 bases + per-thread ldmatrix offsets
    const uint32_t uAh = (uint32_t)__cvta_generic_to_shared(sAh);
    const uint32_t uAl = (uint32_t)__cvta_generic_to_shared(sAl);
    const uint32_t uBh = (uint32_t)__cvta_generic_to_shared(sBh);
    const uint32_t uBl = (uint32_t)__cvta_generic_to_shared(sBl);
    const uint32_t rowOff = (uint32_t)(lane & 15) * LDA + (uint32_t)((lane >> 4) << 4);
    const uint32_t aOff = (uint32_t)warp_m * 32 * LDA + rowOff;
    const uint32_t bOff = (uint32_t)warp_n * 64 * LDA + rowOff;

    // global load mapping: 256 threads, row = t>>1 (0..127), kq = (t&1)*16 elems (32B)
    const int lrow = t >> 1;
    const int lkq = (t & 1) * 16;
    const uint4 zv = make_uint4(0, 0, 0, 0);

    const int arow = row0 + lrow;
    const bool aok = arow < N_NODES;
    const int brow = nbase + lrow;

    for (int k0 = 0; k0 < K; k0 += 32) {
        // ---- stage tiles ----
        {
            const __nv_bfloat16* pa = Ah + (size_t)arow * K + k0 + lkq;
            const __nv_bfloat16* pl = Al + (size_t)arow * K + k0 + lkq;
            uint8_t* da = sAh + lrow * LDA + lkq * 2;
            uint8_t* dl = sAl + lrow * LDA + lkq * 2;
            *(uint4*)(da +  0) = aok ? ((const uint4*)pa)[0] : zv;
            *(uint4*)(da + 16) = aok ? ((const uint4*)pa)[1] : zv;
            *(uint4*)(dl +  0) = aok ? ((const uint4*)pl)[0] : zv;
            *(uint4*)(dl + 16) = aok ? ((const uint4*)pl)[1] : zv;
            const __nv_bfloat16* pb = Bh + (size_t)brow * K + k0 + lkq;
            const __nv_bfloat16* pq = Bl + (size_t)brow * K + k0 + lkq;
            uint8_t* db = sBh + lrow * LDA + lkq * 2;
            uint8_t* dq = sBl + lrow * LDA + lkq * 2;
            *(uint4*)(db +  0) = ((const uint4*)pb)[0];
            *(uint4*)(db + 16) = ((const uint4*)pb)[1];
            *(uint4*)(dq +  0) = ((const uint4*)pq)[0];
            *(uint4*)(dq + 16) = ((const uint4*)pq)[1];
        }
        __syncthreads();

#pragma unroll
        for (int kk = 0; kk < 2; kk++) {
            const uint32_t kb = kk * 32;  // 16 elems * 2B
            uint32_t aH[2][4], aL[2][4], bH[4][4], bL[4][4];
#pragma unroll
            for (int mt = 0; mt < 2; mt++) ldsm4(aH[mt], uAh + aOff + mt * 16 * LDA + kb);
#pragma unroll
            for (int p = 0; p < 4; p++) ldsm4(bH[p], uBh + bOff + p * 16 * LDA + kb);
#pragma unroll
            for (int mt = 0; mt < 2; mt++)
#pragma unroll
                for (int p = 0; p < 4; p++) {
                    mma16816(acc[mt][2 * p + 0], aH[mt], bH[p][0], bH[p][2]);
                    mma16816(acc[mt][2 * p + 1], aH[mt], bH[p][1], bH[p][3]);
                }
#pragma unroll
            for (int p = 0; p < 4; p++) ldsm4(bL[p], uBl + bOff + p * 16 * LDA + kb);
#pragma unroll
            for (int mt = 0; mt < 2; mt++)
#pragma unroll
                for (int p = 0; p < 4; p++) {
                    mma16816(acc[mt][2 * p + 0], aH[mt], bL[p][0], bL[p][2]);
                    mma16816(acc[mt][2 * p + 1], aH[mt], bL[p][1], bL[p][3]);
                }
#pragma unroll
            for (int mt = 0; mt < 2; mt++) ldsm4(aL[mt], uAl + aOff + mt * 16 * LDA + kb);
#pragma unroll
            for (int mt = 0; mt < 2; mt++)
#pragma unroll
                for (int p = 0; p < 4; p++) {
                    mma16816(acc[mt][2 * p + 0], aL[mt], bH[p][0], bH[p][2]);
                    mma16816(acc[mt][2 * p + 1], aL[mt], bH[p][1], bH[p][3]);
                }
        }
        __syncthreads();
    }

    // ---- epilogue: write C + fused attention scores (warp cols = exactly one head) ----
    const int g = lane >> 2;        // row group
    const int tig = lane & 3;
    const int head = blockIdx.x * 2 + warp_n;
    const int cihb = tig * 2;       // col-in-head base offset within nt tile

#pragma unroll
    for (int mt = 0; mt < 2; mt++) {
#pragma unroll
        for (int half = 0; half < 2; half++) {
            int grow = row0 + warp_m * 32 + mt * 16 + g + half * 8;
            if (grow >= N_NODES) continue;
            float sl = 0.f, sr = 0.f;
            float* cp = C + (size_t)grow * 256 + nbase + warp_n * 64;
#pragma unroll
            for (int nt = 0; nt < 8; nt++) {
                float c0 = acc[mt][nt][half * 2 + 0];
                float c1 = acc[mt][nt][half * 2 + 1];
                int cih = nt * 8 + cihb;
                *(float2*)(cp + cih) = make_float2(c0, c1);
                sl += c0 * alw[head * 64 + cih] + c1 * alw[head * 64 + cih + 1];
                sr += c0 * arw[head * 64 + cih] + c1 * arw[head * 64 + cih + 1];
            }
            sl += __shfl_xor_sync(0xffffffffu, sl, 1);
            sl += __shfl_xor_sync(0xffffffffu, sl, 2);
            sr += __shfl_xor_sync(0xffffffffu, sr, 1);
            sr += __shfl_xor_sync(0xffffffffu, sr, 2);
            if (tig == 0) {
                atomicAdd(&g_el[grow * 4 + head], sl);
                atomicAdd(&g_er[grow * 4 + head], sr);
            }
        }
    }
}

// ---------------- fused edge softmax + aggregate + ELU + bf16 split ----------------
__global__ void __launch_bounds__(128) aggregate_k(const float* __restrict__ h,
                                                   float* __restrict__ out, int N) {
    int v = (blockIdx.x * 128 + threadIdx.x) >> 5;
    int lane = threadIdx.x & 31;
    if (v >= N) return;
    int hd = lane >> 3;

    float4 er4 = ((const float4*)g_er)[v];
    float erv = (hd == 0) ? er4.x : (hd == 1) ? er4.y : (hd == 2) ? er4.z : er4.w;

    int r0 = g_rowptr[v];
    int r1 = g_rowptr[v + 1];

    float m = -INFINITY;
    for (int j = r0; j < r1; j++) {
        int s = g_csr_src[j];
        float4 el4 = ((const float4*)g_el)[s];
        float elv = (hd == 0) ? el4.x : (hd == 1) ? el4.y : (hd == 2) ? el4.z : el4.w;
        float e = elv + erv;
        e = (e > 0.f) ? e : 0.2f * e;
        m = fmaxf(m, e);
    }

    float ssum = 0.f;
    float4 acca = make_float4(0.f, 0.f, 0.f, 0.f);
    float4 accb = make_float4(0.f, 0.f, 0.f, 0.f);
    for (int j = r0; j < r1; j++) {
        int s = g_csr_src[j];
        float4 el4 = ((const float4*)g_el)[s];
        float elv = (hd == 0) ? el4.x : (hd == 1) ? el4.y : (hd == 2) ? el4.z : el4.w;
        float e = elv + erv;
        e = (e > 0.f) ? e : 0.2f * e;
        float wgt = __expf(e - m);
        ssum += wgt;
        const float4* hp = (const float4*)(h + (size_t)s * HH + lane * 8);
        float4 ha = hp[0], hb = hp[1];
        acca.x += wgt * ha.x; acca.y += wgt * ha.y;
        acca.z += wgt * ha.z; acca.w += wgt * ha.w;
        accb.x += wgt * hb.x; accb.y += wgt * hb.y;
        accb.z += wgt * hb.z; accb.w += wgt * hb.w;
    }

    float inv = 1.f / (ssum + 1e-9f);
    float o[8] = {acca.x * inv, acca.y * inv, acca.z * inv, acca.w * inv,
                  accb.x * inv, accb.y * inv, accb.z * inv, accb.w * inv};
#pragma unroll
    for (int i = 0; i < 8; i++) o[i] = (o[i] > 0.f) ? o[i] : expm1f(o[i]);

    float* op = out + (size_t)v * HH + lane * 8;
    *(float4*)(op + 0) = make_float4(o[0], o[1], o[2], o[3]);
    *(float4*)(op + 4) = make_float4(o[4], o[5], o[6], o[7]);

    __nv_bfloat16 hi[8], lo[8];
#pragma unroll
    for (int i = 0; i < 8; i++) {
        hi[i] = __float2bfloat16(o[i]);
        lo[i] = __float2bfloat16(o[i] - __bfloat162float(hi[i]));
    }
    *(uint4*)(g_a_hi + (size_t)v * 256 + lane * 8) = *(const uint4*)hi;
    *(uint4*)(g_a_lo + (size_t)v * 256 + lane * 8) = *(const uint4*)lo;
}

// ---------------- final head ----------------
__global__ void __launch_bounds__(128) final_k(const float* __restrict__ feats,
                                               const float* __restrict__ Wout,
                                               const float* __restrict__ bout,
                                               float* __restrict__ out, int N) {
    int v = (blockIdx.x * 128 + threadIdx.x) >> 5;
    int lane = threadIdx.x & 31;
    if (v >= N) return;
    int idx = lane * 8;
    const float4* fp = (const float4*)(feats + (size_t)v * HH + idx);
    float4 fa = fp[0], fb = fp[1];
    const float4* wp = (const float4*)(Wout + (idx & 63));
    float4 wa = wp[0], wb = wp[1];
    float s = fa.x * wa.x + fa.y * wa.y + fa.z * wa.z + fa.w * wa.w +
              fb.x * wb.x + fb.y * wb.y + fb.z * wb.z + fb.w * wb.w;
#pragma unroll
    for (int off = 16; off >= 1; off >>= 1) s += __shfl_down_sync(0xffffffffu, s, off);
    if (lane == 0) {
        float r = 0.25f * s + bout[0];
        out[v] = (r > 0.f) ? r : 0.f;
    }
}

// ---------------- launch ----------------
extern "C" void kernel_launch(void* const* d_in, const int* in_sizes, int n_in,
                              void* d_out, int out_size) {
    const float* x    = (const float*)d_in[0];
    const int*   src  = (const int*)d_in[1];
    const int*   dst  = (const int*)d_in[2];
    const float* W0   = (const float*)d_in[3];
    const float* al0  = (const float*)d_in[4];
    const float* ar0  = (const float*)d_in[5];
    const float* W1   = (const float*)d_in[6];
    const float* al1  = (const float*)d_in[7];
    const float* ar1  = (const float*)d_in[8];
    const float* W2   = (const float*)d_in[9];
    const float* al2  = (const float*)d_in[10];
    const float* ar2  = (const float*)d_in[11];
    const float* Wout = (const float*)d_in[12];
    const float* bout = (const float*)d_in[13];

    const int N = N_NODES;
    const int E = N_EDGES;

    float *h, *h2;
    __nv_bfloat16 *ah, *al, *wh, *wl;
    cudaGetSymbolAddress((void**)&h, g_h);
    cudaGetSymbolAddress((void**)&h2, g_h2);
    cudaGetSymbolAddress((void**)&ah, g_a_hi);
    cudaGetSymbolAddress((void**)&al, g_a_lo);
    cudaGetSymbolAddress((void**)&wh, g_w_hi);
    cudaGetSymbolAddress((void**)&wl, g_w_lo);

    // CSR (dst-sorted)
    zero_counts_k<<<(N + 255) / 256, 256>>>();
    hist_k<<<(E + 255) / 256, 256>>>(dst, E);
    scan_k<<<1, 1024>>>();
    zero_counts_k<<<(N + 255) / 256, 256>>>();
    scatter_k<<<(E + 255) / 256, 256>>>(src, dst, E);

    // operand conversions
    convert_x_k<<<(N * 128 + 255) / 256, 256>>>(x, N * 128);
    convert_w_k<<<(128 * 256 + 255) / 256, 256>>>(W0, 128, wh + 0 * 65536, wl + 0 * 65536);
    convert_w_k<<<(256 * 256 + 255) / 256, 256>>>(W1, 256, wh + 1 * 65536, wl + 1 * 65536);
    convert_w_k<<<(256 * 256 + 255) / 256, 256>>>(W2, 256, wh + 2 * 65536, wl + 2 * 65536);

    dim3 ggrid(2, (N + 127) / 128);
    const int warpGrid = (N + 3) / 4;
    const int zsGrid = (N * NHEADS + 255) / 256;

    // layer 0 (K=128)
    zero_scores_k<<<zsGrid, 256>>>();
    gemm_mma_k<128><<<ggrid, 256>>>(ah, al, wh + 0 * 65536, wl + 0 * 65536, h, al0, ar0);
    aggregate_k<<<warpGrid, 128>>>(h, h2, N);
    // layer 1 (K=256)
    zero_scores_k<<<zsGrid, 256>>>();
    gemm_mma_k<256><<<ggrid, 256>>>(ah, al, wh + 1 * 65536, wl + 1 * 65536, h, al1, ar1);
    aggregate_k<<<warpGrid, 128>>>(h, h2, N);
    // layer 2 (K=256)
    zero_scores_k<<<zsGrid, 256>>>();
    gemm_mma_k<256><<<ggrid, 256>>>(ah, al, wh + 2 * 65536, wl + 2 * 65536, h, al2, ar2);
    aggregate_k<<<warpGrid, 128>>>(h, h2, N);
    // output head
    final_k<<<warpGrid, 128>>>(h2, Wout, bout, (float*)d_out, N);
}